// round 11
// baseline (speedup 1.0000x reference)
#include <cuda_runtime.h>
#include <cuda_fp16.h>

#define Nn   8192
#define FIN  512
#define NHID 128
#define NCLS 64
#define CPRE 16

// ---------------- scratch globals ----------------
__device__ float    g_Wh1[Nn][256];
__device__ float    g_f1h[2][Nn];
__device__ float    g_f2h[2][Nn];
__device__ unsigned g_max1[2];
__device__ float    g_h[Nn][256];
__device__ float    g_Wh2[Nn][64];
__device__ float    g_f1b[Nn];
__device__ float    g_f2b[Nn];
__device__ unsigned g_max2;
__device__ float    g_mu[Nn][64];
__device__ unsigned g_adjb[Nn * 256];
__device__ __half   g_WhH[Nn * 256];
__device__ __half   g_WhL[Nn * 256];
__device__ __half   g_W2h[Nn * 64];
__device__ __half   g_W2l[Nn * 64];
__device__ __half   g_muh[Nn * 64];
__device__ __half   g_mul[Nn * 64];
__device__ float2   g_AC[2][Nn];
__device__ float2   g_BD[2][Nn];
__device__ __half   g_xH[Nn * FIN];
__device__ __half   g_xL[Nn * FIN];

// ---------------- helpers ----------------
__device__ __forceinline__ unsigned enc_f(float f) {
    unsigned u = __float_as_uint(f);
    return (u & 0x80000000u) ? ~u : (u | 0x80000000u);
}
__device__ __forceinline__ float dec_f(unsigned u) {
    return __uint_as_float((u & 0x80000000u) ? (u & 0x7fffffffu) : ~u);
}
__device__ __forceinline__ float eluf(float x) { return x > 0.f ? x : expm1f(x); }

__device__ __forceinline__ void mma16816(float* d, unsigned a0, unsigned a1,
                                         unsigned a2, unsigned a3,
                                         unsigned b0, unsigned b1) {
    asm volatile("mma.sync.aligned.m16n8k16.row.col.f32.f16.f16.f32 "
                 "{%0,%1,%2,%3},{%4,%5,%6,%7},{%8,%9},{%0,%1,%2,%3};\n"
                 : "+f"(d[0]), "+f"(d[1]), "+f"(d[2]), "+f"(d[3])
                 : "r"(a0), "r"(a1), "r"(a2), "r"(a3), "r"(b0), "r"(b1));
}
__device__ __forceinline__ void ldsm4t(unsigned& r0, unsigned& r1, unsigned& r2,
                                       unsigned& r3, const void* p) {
    unsigned a = (unsigned)__cvta_generic_to_shared(p);
    asm volatile("ldmatrix.sync.aligned.m8n8.x4.trans.shared.b16 {%0,%1,%2,%3},[%4];\n"
                 : "=r"(r0), "=r"(r1), "=r"(r2), "=r"(r3) : "r"(a));
}
__device__ __forceinline__ void ldsm4(unsigned& r0, unsigned& r1, unsigned& r2,
                                      unsigned& r3, const void* p) {
    unsigned a = (unsigned)__cvta_generic_to_shared(p);
    asm volatile("ldmatrix.sync.aligned.m8n8.x4.shared.b16 {%0,%1,%2,%3},[%4];\n"
                 : "=r"(r0), "=r"(r1), "=r"(r2), "=r"(r3) : "r"(a));
}
__device__ __forceinline__ void split2(float x, float y, unsigned& hi, unsigned& lo) {
    __half2 h = __floats2half2_rn(x, y);
    float2 f = __half22float2(h);
    __half2 l = __floats2half2_rn(x - f.x, y - f.y);
    hi = *(unsigned*)&h; lo = *(unsigned*)&l;
}
__device__ __forceinline__ void cpa16(unsigned dst, const void* src) {
    asm volatile("cp.async.cg.shared.global [%0], [%1], 16;\n" :: "r"(dst), "l"(src));
}
#define CPA_COMMIT() asm volatile("cp.async.commit_group;\n")

__global__ void k_init() { g_max1[0] = 0u; g_max1[1] = 0u; g_max2 = 0u; }

// ---------------- pack adj to bits ----------------
__global__ void __launch_bounds__(256) k_pack(const int* __restrict__ adj) {
    int row = blockIdx.x, w = threadIdx.x >> 5, lane = threadIdx.x & 31;
    const int* rp = adj + (size_t)row * Nn + w * 1024;
#pragma unroll 4
    for (int it = 0; it < 32; it++) {
        unsigned b = __ballot_sync(0xffffffffu, rp[it * 32 + lane] != 0);
        if (lane == 0) g_adjb[row * 256 + w * 32 + it] = b;
    }
}

// ---------------- split x into fp16 hi/lo ----------------
__global__ void __launch_bounds__(256) k_splitx(const float* __restrict__ x) {
    size_t i = ((size_t)blockIdx.x * 256 + threadIdx.x) * 4;
    float4 v = *(const float4*)&x[i];
    unsigned hh, ll;
    split2(v.x, v.y, hh, ll);
    *(unsigned*)&g_xH[i] = hh; *(unsigned*)&g_xL[i] = ll;
    split2(v.z, v.w, hh, ll);
    *(unsigned*)&g_xH[i + 2] = hh; *(unsigned*)&g_xL[i + 2] = ll;
}

// ---------------- K1: Wh1 = x @ W on tensor cores (3-term fp16 split) --------
// CTA: 128 m-rows x 128 n-cols (blockIdx.y = head). 8 warps = 4m x 2n.
__global__ void __launch_bounds__(256) k_gemm1_tc(const float* __restrict__ W) {
    __shared__ __half xh[128 * 40], xl[128 * 40];     // [m][k], pad 40
    __shared__ __half wh[32 * 136], wl[32 * 136];     // [k][n], pad 136
    int tid = threadIdx.x, w = tid >> 5, lane = tid & 31;
    int wm = w & 3, wn = w >> 2;
    int i0 = blockIdx.x * 128;
    const float* Wp = W + (size_t)blockIdx.y * FIN * NHID;
    float acc[2][8][4] = {};
    for (int k0 = 0; k0 < FIN; k0 += 32) {
        __syncthreads();
        // stage x tiles: 128 rows x 32 k (each thread: 1 row, 16 halves via 2x int4)
        {
            int r = tid >> 1, c8 = (tid & 1) * 16;
            *(int4*)&xh[r * 40 + c8] = *(const int4*)&g_xH[(size_t)(i0 + r) * FIN + k0 + c8];
            *(int4*)&xh[r * 40 + c8 + 8] = *(const int4*)&g_xH[(size_t)(i0 + r) * FIN + k0 + c8 + 8];
            *(int4*)&xl[r * 40 + c8] = *(const int4*)&g_xL[(size_t)(i0 + r) * FIN + k0 + c8];
            *(int4*)&xl[r * 40 + c8 + 8] = *(const int4*)&g_xL[(size_t)(i0 + r) * FIN + k0 + c8 + 8];
        }
        // stage W tile: 32 k-rows x 128 n, split on the fly (each thread 16 floats)
        {
            int r = tid >> 3, c0 = (tid & 7) * 16;
#pragma unroll
            for (int c = 0; c < 16; c += 2) {
                float2 v = *(const float2*)&Wp[(size_t)(k0 + r) * NHID + c0 + c];
                unsigned hh, ll;
                split2(v.x, v.y, hh, ll);
                *(unsigned*)&wh[r * 136 + c0 + c] = hh;
                *(unsigned*)&wl[r * 136 + c0 + c] = ll;
            }
        }
        __syncthreads();
#pragma unroll
        for (int ks = 0; ks < 2; ks++) {
            int kk = ks * 16;
            unsigned ah[2][4], al[2][4];
#pragma unroll
            for (int mt = 0; mt < 2; mt++) {
                int arow = wm * 32 + mt * 16 + (lane & 15);
                int ac = kk + (lane >> 4) * 8;
                ldsm4(ah[mt][0], ah[mt][1], ah[mt][2], ah[mt][3], &xh[arow * 40 + ac]);
                ldsm4(al[mt][0], al[mt][1], al[mt][2], al[mt][3], &xl[arow * 40 + ac]);
            }
            int krow = kk + (lane & 15), cofs = (lane >> 4) * 8;
#pragma unroll
            for (int ng = 0; ng < 4; ng++) {
                int n0 = wn * 64 + ng * 16;
                unsigned bh0, bh1, bh2, bh3, bl0, bl1, bl2, bl3;
                ldsm4t(bh0, bh1, bh2, bh3, &wh[krow * 136 + n0 + cofs]);
                ldsm4t(bl0, bl1, bl2, bl3, &wl[krow * 136 + n0 + cofs]);
#pragma unroll
                for (int mt = 0; mt < 2; mt++) {
                    mma16816(acc[mt][2 * ng], ah[mt][0], ah[mt][1], ah[mt][2], ah[mt][3], bh0, bh1);
                    mma16816(acc[mt][2 * ng], al[mt][0], al[mt][1], al[mt][2], al[mt][3], bh0, bh1);
                    mma16816(acc[mt][2 * ng], ah[mt][0], ah[mt][1], ah[mt][2], ah[mt][3], bl0, bl1);
                    mma16816(acc[mt][2 * ng + 1], ah[mt][0], ah[mt][1], ah[mt][2], ah[mt][3], bh2, bh3);
                    mma16816(acc[mt][2 * ng + 1], al[mt][0], al[mt][1], al[mt][2], al[mt][3], bh2, bh3);
                    mma16816(acc[mt][2 * ng + 1], ah[mt][0], ah[mt][1], ah[mt][2], ah[mt][3], bl2, bl3);
                }
            }
        }
    }
    // epilogue: write fp32 Wh1 + hi/lo halves
    int cbase = blockIdx.y * NHID + wn * 64;
#pragma unroll
    for (int mt = 0; mt < 2; mt++) {
        int gi = i0 + wm * 32 + mt * 16 + (lane >> 2);
#pragma unroll
        for (int nt = 0; nt < 8; nt++) {
            int gc = cbase + nt * 8 + 2 * (lane & 3);
            *(float2*)&g_Wh1[gi][gc] = make_float2(acc[mt][nt][0], acc[mt][nt][1]);
            *(float2*)&g_Wh1[gi + 8][gc] = make_float2(acc[mt][nt][2], acc[mt][nt][3]);
            unsigned hh, ll;
            split2(acc[mt][nt][0], acc[mt][nt][1], hh, ll);
            *(unsigned*)&g_WhH[(size_t)gi * 256 + gc] = hh;
            *(unsigned*)&g_WhL[(size_t)gi * 256 + gc] = ll;
            split2(acc[mt][nt][2], acc[mt][nt][3], hh, ll);
            *(unsigned*)&g_WhH[(size_t)(gi + 8) * 256 + gc] = hh;
            *(unsigned*)&g_WhL[(size_t)(gi + 8) * 256 + gc] = ll;
        }
    }
}

// ---------------- K2: f1,f2 + max (split now done in gemm1 epilogue) --------
__global__ void __launch_bounds__(256) k_fheads(const float* __restrict__ a_heads) {
    int tid = threadIdx.x, w = tid >> 5, lane = tid & 31;
    int row = blockIdx.x * 8 + w;
    float4 w0 = *(const float4*)&g_Wh1[row][lane * 4];
    float4 w1 = *(const float4*)&g_Wh1[row][NHID + lane * 4];
    float4 a0s = *(const float4*)&a_heads[lane * 4];
    float4 a0t = *(const float4*)&a_heads[NHID + lane * 4];
    float4 a1s = *(const float4*)&a_heads[2 * NHID + lane * 4];
    float4 a1t = *(const float4*)&a_heads[3 * NHID + lane * 4];
    float f10 = w0.x * a0s.x + w0.y * a0s.y + w0.z * a0s.z + w0.w * a0s.w;
    float f20 = w0.x * a0t.x + w0.y * a0t.y + w0.z * a0t.z + w0.w * a0t.w;
    float f11 = w1.x * a1s.x + w1.y * a1s.y + w1.z * a1s.z + w1.w * a1s.w;
    float f21 = w1.x * a1t.x + w1.y * a1t.y + w1.z * a1t.z + w1.w * a1t.w;
#pragma unroll
    for (int off = 16; off; off >>= 1) {
        f10 += __shfl_xor_sync(0xffffffffu, f10, off);
        f20 += __shfl_xor_sync(0xffffffffu, f20, off);
        f11 += __shfl_xor_sync(0xffffffffu, f11, off);
        f21 += __shfl_xor_sync(0xffffffffu, f21, off);
    }
    __shared__ float s0[8], s1[8];
    if (lane == 0) {
        g_f1h[0][row] = f10; g_f2h[0][row] = f20;
        g_f1h[1][row] = f11; g_f2h[1][row] = f21;
        s0[w] = f20; s1[w] = f21;
    }
    __syncthreads();
    if (tid == 0) {
        float m0 = s0[0], m1 = s1[0];
#pragma unroll
        for (int k = 1; k < 8; k++) { m0 = fmaxf(m0, s0[k]); m1 = fmaxf(m1, s1[k]); }
        atomicMax(&g_max1[0], enc_f(m0));
        atomicMax(&g_max1[1], enc_f(m1));
    }
}

// ---------------- AC/BD factor kernels ----------------
__global__ void __launch_bounds__(256) k_acbd1() {
    int row = blockIdx.x * 256 + threadIdx.x;
#pragma unroll
    for (int h = 0; h < 2; h++) {
        float F = dec_f(g_max1[h]);
        float u = g_f1h[h][row] + F;
        g_AC[h][row] = make_float2(expf(0.8f * fminf(u, 0.f)),
                                   expf(-0.8f * fmaxf(u, 0.f)));
        float t = g_f2h[h][row] - F;
        g_BD[h][row] = make_float2(expf(t), expf(0.2f * t));
    }
}
__global__ void __launch_bounds__(256) k_acbd2() {
    int row = blockIdx.x * 256 + threadIdx.x;
    float F = dec_f(g_max2);
    float u = g_f1b[row] + F;
    g_AC[0][row] = make_float2(expf(0.8f * fminf(u, 0.f)),
                               expf(-0.8f * fmaxf(u, 0.f)));
    float t = g_f2b[row] - F;
    g_BD[0][row] = make_float2(expf(t), expf(0.2f * t));
}

// ---------------- tensor-core attention, cp.async double-buffered ----------------
template <int NH, int FO>
__global__ void __launch_bounds__(256) k_attn_tc(float* __restrict__ outB) {
    constexpr int LD = NH * FO;
    constexpr int PADL = LD + 8;
    constexpr int NCW = (NH == 2) ? FO : FO / 2;
    constexpr int NTT = NCW / 8;
    constexpr int STAGE = 2 * 64 * PADL;
    extern __shared__ __half sm[];
    float2* bdAll = (float2*)(sm + 2 * STAGE);

    const __half* WH = (NH == 2) ? g_WhH : g_W2h;
    const __half* WL = (NH == 2) ? g_WhL : g_W2l;
    int tid = threadIdx.x, w = tid >> 5, lane = tid & 31;
    int q = lane & 3, rl = lane >> 2;
    int hd = (NH == 2) ? (w >> 2) : 0;
    int nb = (NH == 2) ? hd * FO : (w >> 2) * NCW;
    int i0 = blockIdx.x * 64;
    int gr0 = i0 + (w & 3) * 16 + rl, gr1 = gr0 + 8;
    float2 ac0 = g_AC[hd][gr0], ac1 = g_AC[hd][gr1];
    const unsigned* adjR0 = g_adjb + gr0 * 256;
    const unsigned* adjR1 = g_adjb + gr1 * 256;
    unsigned smbase = (unsigned)__cvta_generic_to_shared(sm);
    unsigned bdbase = (unsigned)__cvta_generic_to_shared(bdAll);

    float acc[NTT][4];
#pragma unroll
    for (int i = 0; i < NTT; i++)
#pragma unroll
        for (int j = 0; j < 4; j++) acc[i][j] = 0.f;
    float ls0 = 0.f, ls1 = 0.f;

    auto preload = [&](int jc, int s) {
        for (int t = tid; t < 64 * (LD / 8); t += 256) {
            int r = t / (LD / 8), c8 = (t % (LD / 8)) * 8;
            cpa16(smbase + (s * STAGE + r * PADL + c8) * 2,
                  &WH[(size_t)(jc + r) * LD + c8]);
            cpa16(smbase + (s * STAGE + 64 * PADL + r * PADL + c8) * 2,
                  &WL[(size_t)(jc + r) * LD + c8]);
        }
        if (tid < NH * 32) {
            int hh = tid >> 5, off = (tid & 31) * 2;
            cpa16(bdbase + (s * NH * 64 + hh * 64 + off) * 8,
                  &g_BD[hh][jc + off]);
        }
    };

    preload(0, 0);
    CPA_COMMIT();
    unsigned mA0 = adjR0[0], mA1 = adjR0[1];
    unsigned mB0 = adjR1[0], mB1 = adjR1[1];

    for (int c = 0; c < Nn / 64; c++) {
        int s = c & 1;
        if (c + 1 < Nn / 64) {
            preload((c + 1) * 64, s ^ 1);
            CPA_COMMIT();
            asm volatile("cp.async.wait_group 1;\n");
        } else {
            asm volatile("cp.async.wait_group 0;\n");
        }
        __syncthreads();
        unsigned cA0 = mA0, cA1 = mA1, cB0 = mB0, cB1 = mB1;
        if (c + 1 < Nn / 64) {
            int b = (c + 1) * 2;
            mA0 = adjR0[b]; mA1 = adjR0[b + 1];
            mB0 = adjR1[b]; mB1 = adjR1[b + 1];
        }
        __half* WHs = sm + s * STAGE;
        __half* WLs = WHs + 64 * PADL;
        float2* bdS = bdAll + s * NH * 64;
#pragma unroll
        for (int sub = 0; sub < 4; sub++) {
            unsigned mw0 = (sub < 2) ? cA0 : cA1;
            unsigned mw1 = (sub < 2) ? cB0 : cB1;
            int o = (sub & 1) * 16;
            float4 bd0 = *(float4*)&bdS[hd * 64 + sub * 16 + 2 * q];
            float4 bd8 = *(float4*)&bdS[hd * 64 + sub * 16 + 2 * q + 8];
            float p00 = (mw0 >> (o + 2 * q)) & 1 ? fmaxf(ac0.x * bd0.x, ac0.y * bd0.y) : 0.f;
            float p01 = (mw0 >> (o + 2 * q + 1)) & 1 ? fmaxf(ac0.x * bd0.z, ac0.y * bd0.w) : 0.f;
            float p02 = (mw0 >> (o + 2 * q + 8)) & 1 ? fmaxf(ac0.x * bd8.x, ac0.y * bd8.y) : 0.f;
            float p03 = (mw0 >> (o + 2 * q + 9)) & 1 ? fmaxf(ac0.x * bd8.z, ac0.y * bd8.w) : 0.f;
            float p10 = (mw1 >> (o + 2 * q)) & 1 ? fmaxf(ac1.x * bd0.x, ac1.y * bd0.y) : 0.f;
            float p11 = (mw1 >> (o + 2 * q + 1)) & 1 ? fmaxf(ac1.x * bd0.z, ac1.y * bd0.w) : 0.f;
            float p12 = (mw1 >> (o + 2 * q + 8)) & 1 ? fmaxf(ac1.x * bd8.x, ac1.y * bd8.y) : 0.f;
            float p13 = (mw1 >> (o + 2 * q + 9)) & 1 ? fmaxf(ac1.x * bd8.z, ac1.y * bd8.w) : 0.f;
            ls0 += p00 + p01 + p02 + p03;
            ls1 += p10 + p11 + p12 + p13;
            unsigned aH[4], aL[4];
            split2(p00, p01, aH[0], aL[0]);
            split2(p10, p11, aH[1], aL[1]);
            split2(p02, p03, aH[2], aL[2]);
            split2(p12, p13, aH[3], aL[3]);
            int krow = sub * 16 + (lane & 15), cofs = (lane >> 4) * 8;
#pragma unroll
            for (int ng = 0; ng < NTT / 2; ng++) {
                int n0 = nb + ng * 16;
                unsigned bh0, bh1, bh2, bh3, bl0, bl1, bl2, bl3;
                ldsm4t(bh0, bh1, bh2, bh3, &WHs[krow * PADL + n0 + cofs]);
                ldsm4t(bl0, bl1, bl2, bl3, &WLs[krow * PADL + n0 + cofs]);
                mma16816(acc[2 * ng], aH[0], aH[1], aH[2], aH[3], bh0, bh1);
                mma16816(acc[2 * ng], aL[0], aL[1], aL[2], aL[3], bh0, bh1);
                mma16816(acc[2 * ng], aH[0], aH[1], aH[2], aH[3], bl0, bl1);
                mma16816(acc[2 * ng + 1], aH[0], aH[1], aH[2], aH[3], bh2, bh3);
                mma16816(acc[2 * ng + 1], aL[0], aL[1], aL[2], aL[3], bh2, bh3);
                mma16816(acc[2 * ng + 1], aH[0], aH[1], aH[2], aH[3], bl2, bl3);
            }
        }
        __syncthreads();
    }
    ls0 += __shfl_xor_sync(0xffffffffu, ls0, 1);
    ls0 += __shfl_xor_sync(0xffffffffu, ls0, 2);
    ls1 += __shfl_xor_sync(0xffffffffu, ls1, 1);
    ls1 += __shfl_xor_sync(0xffffffffu, ls1, 2);
    float inv0 = 1.f / ls0, inv1 = 1.f / ls1;
    float* outA = (NH == 2) ? &g_h[0][0] : &g_mu[0][0];
#pragma unroll
    for (int nt = 0; nt < NTT; nt++) {
        int c = nb + nt * 8 + 2 * q;
        float m00 = eluf(acc[nt][0] * inv0), m01 = eluf(acc[nt][1] * inv0);
        float m10 = eluf(acc[nt][2] * inv1), m11 = eluf(acc[nt][3] * inv1);
        *(float2*)&outA[(size_t)gr0 * LD + c] = make_float2(m00, m01);
        *(float2*)&outA[(size_t)gr1 * LD + c] = make_float2(m10, m11);
        if (NH == 1) {
            *(float2*)&outB[(size_t)gr0 * LD + c] = make_float2(m00, m01);
            *(float2*)&outB[(size_t)gr1 * LD + c] = make_float2(m10, m11);
            unsigned h0, l0, h1, l1;
            split2(m00, m01, h0, l0);
            split2(m10, m11, h1, l1);
            *(unsigned*)&g_muh[(size_t)gr0 * 64 + c] = h0;
            *(unsigned*)&g_mul[(size_t)gr0 * 64 + c] = l0;
            *(unsigned*)&g_muh[(size_t)gr1 * 64 + c] = h1;
            *(unsigned*)&g_mul[(size_t)gr1 * 64 + c] = l1;
        }
    }
}

// ---------------- K5: Wh2 = h @ W_out ----------------
__global__ void __launch_bounds__(256) k_gemm2(const float* __restrict__ Wout) {
    __shared__ float hs[4][256];
    __shared__ float ws[64][64];
    int tid = threadIdx.x, i0 = blockIdx.x * 4;
    int r = tid >> 6, c4 = (tid & 63) * 4;
    *(float4*)&hs[r][c4] = *(const float4*)&g_h[i0 + r][c4];
    int c = tid & 63;
    float acc = 0.f;
    for (int k0 = 0; k0 < 256; k0 += 64) {
        __syncthreads();
#pragma unroll
        for (int p = 0; p < 4; p++) {
            int idx = tid + p * 256, kk = idx >> 4, cc = (idx & 15) * 4;
            *(float4*)&ws[kk][cc] = *(const float4*)&Wout[(size_t)(k0 + kk) * NCLS + cc];
        }
        __syncthreads();
#pragma unroll
        for (int kk = 0; kk < 64; kk++) acc += hs[r][k0 + kk] * ws[kk][c];
    }
    g_Wh2[i0 + r][c] = acc;
}

// ---------------- K6: layer-2 f1,f2 + max + split ----------------
__global__ void __launch_bounds__(256) k_fb(const float* __restrict__ a_out) {
    int tid = threadIdx.x, w = tid >> 5, lane = tid & 31;
    int row = blockIdx.x * 8 + w;
    float2 v = *(const float2*)&g_Wh2[row][lane * 2];
    unsigned hh, ll;
    split2(v.x, v.y, hh, ll);
    *(unsigned*)&g_W2h[(size_t)row * 64 + lane * 2] = hh;
    *(unsigned*)&g_W2l[(size_t)row * 64 + lane * 2] = ll;
    float2 as = *(const float2*)&a_out[lane * 2];
    float2 at = *(const float2*)&a_out[NCLS + lane * 2];
    float f1 = v.x * as.x + v.y * as.y;
    float f2 = v.x * at.x + v.y * at.y;
#pragma unroll
    for (int off = 16; off; off >>= 1) {
        f1 += __shfl_xor_sync(0xffffffffu, f1, off);
        f2 += __shfl_xor_sync(0xffffffffu, f2, off);
    }
    __shared__ float sm[8];
    if (lane == 0) { g_f1b[row] = f1; g_f2b[row] = f2; sm[w] = f2; }
    __syncthreads();
    if (tid == 0) {
        float m = sm[0];
#pragma unroll
        for (int k = 1; k < 8; k++) m = fmaxf(m, sm[k]);
        atomicMax(&g_max2, enc_f(m));
    }
}

// ---------------- recon = mu @ mu^T on tensor cores ----------------
__global__ void __launch_bounds__(256) k_recon_tc(float* __restrict__ out) {
    extern __shared__ __half sm[];
    __half* AH = sm;
    __half* AL = AH + 128 * 72;
    __half* BH = AL + 128 * 72;
    __half* BL = BH + 128 * 72;
    int tid = threadIdx.x, w = tid >> 5, lane = tid & 31;
    int i0 = blockIdx.y * 128, j0 = blockIdx.x * 128;
    for (int t = tid; t < 1024; t += 256) {
        int r = t >> 3, c8 = (t & 7) * 8;
        *(int4*)&AH[r * 72 + c8] = *(const int4*)&g_muh[(size_t)(i0 + r) * 64 + c8];
        *(int4*)&AL[r * 72 + c8] = *(const int4*)&g_mul[(size_t)(i0 + r) * 64 + c8];
        *(int4*)&BH[r * 72 + c8] = *(const int4*)&g_muh[(size_t)(j0 + r) * 64 + c8];
        *(int4*)&BL[r * 72 + c8] = *(const int4*)&g_mul[(size_t)(j0 + r) * 64 + c8];
    }
    __syncthreads();
    int wm = w & 3, wn = w >> 2;
    float acc[2][8][4] = {};
#pragma unroll
    for (int ks = 0; ks < 4; ks++) {
        int k0 = ks * 16;
        unsigned ah[2][4], al[2][4];
#pragma unroll
        for (int mt = 0; mt < 2; mt++) {
            int arow = wm * 32 + mt * 16 + (lane & 15);
            int ac = k0 + (lane >> 4) * 8;
            ldsm4(ah[mt][0], ah[mt][1], ah[mt][2], ah[mt][3], &AH[arow * 72 + ac]);
            ldsm4(al[mt][0], al[mt][1], al[mt][2], al[mt][3], &AL[arow * 72 + ac]);
        }
#pragma unroll
        for (int ng = 0; ng < 4; ng++) {
            int brow = wn * 64 + ng * 16 + (lane & 7) + ((lane >> 4) << 3);
            int bc = k0 + ((lane >> 3) & 1) * 8;
            unsigned bh0, bh1, bh2, bh3, bl0, bl1, bl2, bl3;
            ldsm4(bh0, bh1, bh2, bh3, &BH[brow * 72 + bc]);
            ldsm4(bl0, bl1, bl2, bl3, &BL[brow * 72 + bc]);
#pragma unroll
            for (int mt = 0; mt < 2; mt++) {
                mma16816(acc[mt][2 * ng], ah[mt][0], ah[mt][1], ah[mt][2], ah[mt][3], bh0, bh1);
                mma16816(acc[mt][2 * ng], al[mt][0], al[mt][1], al[mt][2], al[mt][3], bh0, bh1);
                mma16816(acc[mt][2 * ng], ah[mt][0], ah[mt][1], ah[mt][2], ah[mt][3], bl0, bl1);
                mma16816(acc[mt][2 * ng + 1], ah[mt][0], ah[mt][1], ah[mt][2], ah[mt][3], bh2, bh3);
                mma16816(acc[mt][2 * ng + 1], al[mt][0], al[mt][1], al[mt][2], al[mt][3], bh2, bh3);
                mma16816(acc[mt][2 * ng + 1], ah[mt][0], ah[mt][1], ah[mt][2], ah[mt][3], bl2, bl3);
            }
        }
    }
#pragma unroll
    for (int mt = 0; mt < 2; mt++) {
        int gi = i0 + wm * 32 + mt * 16 + (lane >> 2);
#pragma unroll
        for (int nt = 0; nt < 8; nt++) {
            int gj = j0 + wn * 64 + nt * 8 + 2 * (lane & 3);
            *(float2*)&out[(size_t)gi * Nn + gj] = make_float2(acc[mt][nt][0], acc[mt][nt][1]);
            *(float2*)&out[(size_t)(gi + 8) * Nn + gj] = make_float2(acc[mt][nt][2], acc[mt][nt][3]);
        }
    }
}

// ---------------- K9: class_pre ----------------
__global__ void __launch_bounds__(256) k_class(const float* __restrict__ W1,
                                               float* __restrict__ outc) {
    __shared__ float w1s[NCLS * CPRE];
    int tid = threadIdx.x, w = tid >> 5, lane = tid & 31;
    *(float4*)&w1s[tid * 4] = *(const float4*)&W1[tid * 4];
    __syncthreads();
    int row = blockIdx.x * 8 + w;
    int c = lane & 15, half = lane >> 4;
    float acc = 0.f;
#pragma unroll
    for (int k = 0; k < 32; k++) {
        int kk = half * 32 + k;
        acc += g_mu[row][kk] * w1s[kk * CPRE + c];
    }
    acc += __shfl_xor_sync(0xffffffffu, acc, 16);
    float m = acc;
#pragma unroll
    for (int off = 8; off; off >>= 1) m = fmaxf(m, __shfl_xor_sync(0xffffffffu, m, off));
    float e = __expf(acc - m);
    float s = e;
#pragma unroll
    for (int off = 8; off; off >>= 1) s += __shfl_xor_sync(0xffffffffu, s, off);
    if (lane < 16) outc[(size_t)row * CPRE + c] = e / s;
}

// ---------------- launch ----------------
extern "C" void kernel_launch(void* const* d_in, const int* in_sizes, int n_in,
                              void* d_out, int out_size) {
    const float* x       = (const float*)d_in[0];
    const int*   adj     = (const int*)d_in[1];
    const float* W_heads = (const float*)d_in[2];
    const float* a_heads = (const float*)d_in[3];
    const float* W_out   = (const float*)d_in[4];
    const float* a_out   = (const float*)d_in[5];
    const float* W1      = (const float*)d_in[6];
    float* out = (float*)d_out;
    float* out_mu    = out + (size_t)Nn * Nn;
    float* out_class = out_mu + (size_t)Nn * NCLS;

    const int SM1 = 2 * (2 * 64 * 264) * 2 + 2 * 2 * 64 * 8;   // 137216
    const int SM2 = 2 * (2 * 64 * 72) * 2 + 2 * 1 * 64 * 8;    //  37888
    const int SMR = 4 * 128 * 72 * 2;                          //  73728
    static bool attr_done = false;
    if (!attr_done) {
        cudaFuncSetAttribute(k_attn_tc<2, 128>, cudaFuncAttributeMaxDynamicSharedMemorySize, SM1);
        cudaFuncSetAttribute(k_attn_tc<1, 64>, cudaFuncAttributeMaxDynamicSharedMemorySize, SM2);
        cudaFuncSetAttribute(k_recon_tc, cudaFuncAttributeMaxDynamicSharedMemorySize, SMR);
        attr_done = true;
    }

    k_init<<<1, 1>>>();
    k_pack<<<Nn, 256>>>(adj);
    k_splitx<<<Nn * FIN / 1024, 256>>>(x);
    k_gemm1_tc<<<dim3(Nn / 128, 2), 256>>>(W_heads);
    k_fheads<<<Nn / 8, 256>>>(a_heads);
    k_acbd1<<<Nn / 256, 256>>>();
    k_attn_tc<2, 128><<<Nn / 64, 256, SM1>>>(nullptr);
    k_gemm2<<<Nn / 4, 256>>>(W_out);
    k_fb<<<Nn / 8, 256>>>(a_out);
    k_acbd2<<<Nn / 256, 256>>>();
    k_attn_tc<1, 64><<<Nn / 64, 256, SM2>>>(out_mu);
    k_recon_tc<<<dim3(Nn / 128, Nn / 128), 256, SMR>>>(out);
    k_class<<<Nn / 8, 256>>>(W1, out_class);
}

// round 12
// speedup vs baseline: 1.0033x; 1.0033x over previous
#include <cuda_runtime.h>
#include <cuda_fp16.h>

#define Nn   8192
#define FIN  512
#define NHID 128
#define NCLS 64
#define CPRE 16

// ---------------- scratch globals ----------------
__device__ float    g_Wh1[Nn][256];
__device__ float    g_f1h[2][Nn];
__device__ float    g_f2h[2][Nn];
__device__ unsigned g_max1[2];
__device__ float    g_h[Nn][256];
__device__ float    g_Wh2[Nn][64];
__device__ float    g_f1b[Nn];
__device__ float    g_f2b[Nn];
__device__ unsigned g_max2;
__device__ float    g_mu[Nn][64];
__device__ unsigned g_adjb[Nn * 256];
__device__ __half   g_WhH[Nn * 256];
__device__ __half   g_WhL[Nn * 256];
__device__ __half   g_W2h[Nn * 64];
__device__ __half   g_W2l[Nn * 64];
__device__ __half   g_muh[Nn * 64];
__device__ __half   g_mul[Nn * 64];
__device__ float2   g_AC[2][Nn];
__device__ float2   g_BD[2][Nn];
__device__ __half   g_xH[Nn * FIN];
__device__ __half   g_xL[Nn * FIN];

// ---------------- helpers ----------------
__device__ __forceinline__ unsigned enc_f(float f) {
    unsigned u = __float_as_uint(f);
    return (u & 0x80000000u) ? ~u : (u | 0x80000000u);
}
__device__ __forceinline__ float dec_f(unsigned u) {
    return __uint_as_float((u & 0x80000000u) ? (u & 0x7fffffffu) : ~u);
}
__device__ __forceinline__ float eluf(float x) { return x > 0.f ? x : expm1f(x); }

__device__ __forceinline__ void mma16816(float* d, unsigned a0, unsigned a1,
                                         unsigned a2, unsigned a3,
                                         unsigned b0, unsigned b1) {
    asm volatile("mma.sync.aligned.m16n8k16.row.col.f32.f16.f16.f32 "
                 "{%0,%1,%2,%3},{%4,%5,%6,%7},{%8,%9},{%0,%1,%2,%3};\n"
                 : "+f"(d[0]), "+f"(d[1]), "+f"(d[2]), "+f"(d[3])
                 : "r"(a0), "r"(a1), "r"(a2), "r"(a3), "r"(b0), "r"(b1));
}
__device__ __forceinline__ void ldsm4t(unsigned& r0, unsigned& r1, unsigned& r2,
                                       unsigned& r3, const void* p) {
    unsigned a = (unsigned)__cvta_generic_to_shared(p);
    asm volatile("ldmatrix.sync.aligned.m8n8.x4.trans.shared.b16 {%0,%1,%2,%3},[%4];\n"
                 : "=r"(r0), "=r"(r1), "=r"(r2), "=r"(r3) : "r"(a));
}
__device__ __forceinline__ void ldsm4(unsigned& r0, unsigned& r1, unsigned& r2,
                                      unsigned& r3, const void* p) {
    unsigned a = (unsigned)__cvta_generic_to_shared(p);
    asm volatile("ldmatrix.sync.aligned.m8n8.x4.shared.b16 {%0,%1,%2,%3},[%4];\n"
                 : "=r"(r0), "=r"(r1), "=r"(r2), "=r"(r3) : "r"(a));
}
__device__ __forceinline__ void split2(float x, float y, unsigned& hi, unsigned& lo) {
    __half2 h = __floats2half2_rn(x, y);
    float2 f = __half22float2(h);
    __half2 l = __floats2half2_rn(x - f.x, y - f.y);
    hi = *(unsigned*)&h; lo = *(unsigned*)&l;
}
__device__ __forceinline__ void cpa16(unsigned dst, const void* src) {
    asm volatile("cp.async.cg.shared.global [%0], [%1], 16;\n" :: "r"(dst), "l"(src));
}
#define CPA_COMMIT() asm volatile("cp.async.commit_group;\n")

__global__ void k_init() { g_max1[0] = 0u; g_max1[1] = 0u; g_max2 = 0u; }

// ---------------- pack adj to bits ----------------
__global__ void __launch_bounds__(256) k_pack(const int* __restrict__ adj) {
    int row = blockIdx.x, w = threadIdx.x >> 5, lane = threadIdx.x & 31;
    const int* rp = adj + (size_t)row * Nn + w * 1024;
#pragma unroll 4
    for (int it = 0; it < 32; it++) {
        unsigned b = __ballot_sync(0xffffffffu, rp[it * 32 + lane] != 0);
        if (lane == 0) g_adjb[row * 256 + w * 32 + it] = b;
    }
}

// ---------------- split x into fp16 hi/lo ----------------
__global__ void __launch_bounds__(256) k_splitx(const float* __restrict__ x) {
    size_t i = ((size_t)blockIdx.x * 256 + threadIdx.x) * 4;
    float4 v = *(const float4*)&x[i];
    unsigned hh, ll;
    split2(v.x, v.y, hh, ll);
    *(unsigned*)&g_xH[i] = hh; *(unsigned*)&g_xL[i] = ll;
    split2(v.z, v.w, hh, ll);
    *(unsigned*)&g_xH[i + 2] = hh; *(unsigned*)&g_xL[i + 2] = ll;
}

// ---------------- K1: Wh1 = x @ W on tensor cores (3-term fp16 split) --------
// CTA: 128 m-rows x 128 n-cols (blockIdx.y = head). 8 warps = 4m x 2n.
__global__ void __launch_bounds__(256) k_gemm1_tc(const float* __restrict__ W) {
    __shared__ __half xh[128 * 40], xl[128 * 40];     // [m][k], pad 40
    __shared__ __half wh[32 * 136], wl[32 * 136];     // [k][n], pad 136
    int tid = threadIdx.x, w = tid >> 5, lane = tid & 31;
    int wm = w & 3, wn = w >> 2;
    int i0 = blockIdx.x * 128;
    const float* Wp = W + (size_t)blockIdx.y * FIN * NHID;
    float acc[2][8][4] = {};
    for (int k0 = 0; k0 < FIN; k0 += 32) {
        __syncthreads();
        // stage x tiles: 128 rows x 32 k (each thread: 1 row, 16 halves via 2x int4)
        {
            int r = tid >> 1, c8 = (tid & 1) * 16;
            *(int4*)&xh[r * 40 + c8] = *(const int4*)&g_xH[(size_t)(i0 + r) * FIN + k0 + c8];
            *(int4*)&xh[r * 40 + c8 + 8] = *(const int4*)&g_xH[(size_t)(i0 + r) * FIN + k0 + c8 + 8];
            *(int4*)&xl[r * 40 + c8] = *(const int4*)&g_xL[(size_t)(i0 + r) * FIN + k0 + c8];
            *(int4*)&xl[r * 40 + c8 + 8] = *(const int4*)&g_xL[(size_t)(i0 + r) * FIN + k0 + c8 + 8];
        }
        // stage W tile: 32 k-rows x 128 n, split on the fly (each thread 16 floats)
        {
            int r = tid >> 3, c0 = (tid & 7) * 16;
#pragma unroll
            for (int c = 0; c < 16; c += 2) {
                float2 v = *(const float2*)&Wp[(size_t)(k0 + r) * NHID + c0 + c];
                unsigned hh, ll;
                split2(v.x, v.y, hh, ll);
                *(unsigned*)&wh[r * 136 + c0 + c] = hh;
                *(unsigned*)&wl[r * 136 + c0 + c] = ll;
            }
        }
        __syncthreads();
#pragma unroll
        for (int ks = 0; ks < 2; ks++) {
            int kk = ks * 16;
            unsigned ah[2][4], al[2][4];
#pragma unroll
            for (int mt = 0; mt < 2; mt++) {
                int arow = wm * 32 + mt * 16 + (lane & 15);
                int ac = kk + (lane >> 4) * 8;
                ldsm4(ah[mt][0], ah[mt][1], ah[mt][2], ah[mt][3], &xh[arow * 40 + ac]);
                ldsm4(al[mt][0], al[mt][1], al[mt][2], al[mt][3], &xl[arow * 40 + ac]);
            }
            int krow = kk + (lane & 15), cofs = (lane >> 4) * 8;
#pragma unroll
            for (int ng = 0; ng < 4; ng++) {
                int n0 = wn * 64 + ng * 16;
                unsigned bh0, bh1, bh2, bh3, bl0, bl1, bl2, bl3;
                ldsm4t(bh0, bh1, bh2, bh3, &wh[krow * 136 + n0 + cofs]);
                ldsm4t(bl0, bl1, bl2, bl3, &wl[krow * 136 + n0 + cofs]);
#pragma unroll
                for (int mt = 0; mt < 2; mt++) {
                    mma16816(acc[mt][2 * ng], ah[mt][0], ah[mt][1], ah[mt][2], ah[mt][3], bh0, bh1);
                    mma16816(acc[mt][2 * ng], al[mt][0], al[mt][1], al[mt][2], al[mt][3], bh0, bh1);
                    mma16816(acc[mt][2 * ng], ah[mt][0], ah[mt][1], ah[mt][2], ah[mt][3], bl0, bl1);
                    mma16816(acc[mt][2 * ng + 1], ah[mt][0], ah[mt][1], ah[mt][2], ah[mt][3], bh2, bh3);
                    mma16816(acc[mt][2 * ng + 1], al[mt][0], al[mt][1], al[mt][2], al[mt][3], bh2, bh3);
                    mma16816(acc[mt][2 * ng + 1], ah[mt][0], ah[mt][1], ah[mt][2], ah[mt][3], bl2, bl3);
                }
            }
        }
    }
    // epilogue: write fp32 Wh1 + hi/lo halves
    int cbase = blockIdx.y * NHID + wn * 64;
#pragma unroll
    for (int mt = 0; mt < 2; mt++) {
        int gi = i0 + wm * 32 + mt * 16 + (lane >> 2);
#pragma unroll
        for (int nt = 0; nt < 8; nt++) {
            int gc = cbase + nt * 8 + 2 * (lane & 3);
            *(float2*)&g_Wh1[gi][gc] = make_float2(acc[mt][nt][0], acc[mt][nt][1]);
            *(float2*)&g_Wh1[gi + 8][gc] = make_float2(acc[mt][nt][2], acc[mt][nt][3]);
            unsigned hh, ll;
            split2(acc[mt][nt][0], acc[mt][nt][1], hh, ll);
            *(unsigned*)&g_WhH[(size_t)gi * 256 + gc] = hh;
            *(unsigned*)&g_WhL[(size_t)gi * 256 + gc] = ll;
            split2(acc[mt][nt][2], acc[mt][nt][3], hh, ll);
            *(unsigned*)&g_WhH[(size_t)(gi + 8) * 256 + gc] = hh;
            *(unsigned*)&g_WhL[(size_t)(gi + 8) * 256 + gc] = ll;
        }
    }
}

// ---------------- K2: f1,f2 + max (split now done in gemm1 epilogue) --------
__global__ void __launch_bounds__(256) k_fheads(const float* __restrict__ a_heads) {
    int tid = threadIdx.x, w = tid >> 5, lane = tid & 31;
    int row = blockIdx.x * 8 + w;
    float4 w0 = *(const float4*)&g_Wh1[row][lane * 4];
    float4 w1 = *(const float4*)&g_Wh1[row][NHID + lane * 4];
    float4 a0s = *(const float4*)&a_heads[lane * 4];
    float4 a0t = *(const float4*)&a_heads[NHID + lane * 4];
    float4 a1s = *(const float4*)&a_heads[2 * NHID + lane * 4];
    float4 a1t = *(const float4*)&a_heads[3 * NHID + lane * 4];
    float f10 = w0.x * a0s.x + w0.y * a0s.y + w0.z * a0s.z + w0.w * a0s.w;
    float f20 = w0.x * a0t.x + w0.y * a0t.y + w0.z * a0t.z + w0.w * a0t.w;
    float f11 = w1.x * a1s.x + w1.y * a1s.y + w1.z * a1s.z + w1.w * a1s.w;
    float f21 = w1.x * a1t.x + w1.y * a1t.y + w1.z * a1t.z + w1.w * a1t.w;
#pragma unroll
    for (int off = 16; off; off >>= 1) {
        f10 += __shfl_xor_sync(0xffffffffu, f10, off);
        f20 += __shfl_xor_sync(0xffffffffu, f20, off);
        f11 += __shfl_xor_sync(0xffffffffu, f11, off);
        f21 += __shfl_xor_sync(0xffffffffu, f21, off);
    }
    __shared__ float s0[8], s1[8];
    if (lane == 0) {
        g_f1h[0][row] = f10; g_f2h[0][row] = f20;
        g_f1h[1][row] = f11; g_f2h[1][row] = f21;
        s0[w] = f20; s1[w] = f21;
    }
    __syncthreads();
    if (tid == 0) {
        float m0 = s0[0], m1 = s1[0];
#pragma unroll
        for (int k = 1; k < 8; k++) { m0 = fmaxf(m0, s0[k]); m1 = fmaxf(m1, s1[k]); }
        atomicMax(&g_max1[0], enc_f(m0));
        atomicMax(&g_max1[1], enc_f(m1));
    }
}

// ---------------- AC/BD factor kernels ----------------
__global__ void __launch_bounds__(256) k_acbd1() {
    int row = blockIdx.x * 256 + threadIdx.x;
#pragma unroll
    for (int h = 0; h < 2; h++) {
        float F = dec_f(g_max1[h]);
        float u = g_f1h[h][row] + F;
        g_AC[h][row] = make_float2(expf(0.8f * fminf(u, 0.f)),
                                   expf(-0.8f * fmaxf(u, 0.f)));
        float t = g_f2h[h][row] - F;
        g_BD[h][row] = make_float2(expf(t), expf(0.2f * t));
    }
}
__global__ void __launch_bounds__(256) k_acbd2() {
    int row = blockIdx.x * 256 + threadIdx.x;
    float F = dec_f(g_max2);
    float u = g_f1b[row] + F;
    g_AC[0][row] = make_float2(expf(0.8f * fminf(u, 0.f)),
                               expf(-0.8f * fmaxf(u, 0.f)));
    float t = g_f2b[row] - F;
    g_BD[0][row] = make_float2(expf(t), expf(0.2f * t));
}

// ---------------- tensor-core attention, cp.async double-buffered ----------------
template <int NH, int FO>
__global__ void __launch_bounds__(256) k_attn_tc(float* __restrict__ outB) {
    constexpr int LD = NH * FO;
    constexpr int PADL = LD + 8;
    constexpr int NCW = (NH == 2) ? FO : FO / 2;
    constexpr int NTT = NCW / 8;
    constexpr int STAGE = 2 * 64 * PADL;
    extern __shared__ __half sm[];
    float2* bdAll = (float2*)(sm + 2 * STAGE);

    const __half* WH = (NH == 2) ? g_WhH : g_W2h;
    const __half* WL = (NH == 2) ? g_WhL : g_W2l;
    int tid = threadIdx.x, w = tid >> 5, lane = tid & 31;
    int q = lane & 3, rl = lane >> 2;
    int hd = (NH == 2) ? (w >> 2) : 0;
    int nb = (NH == 2) ? hd * FO : (w >> 2) * NCW;
    int i0 = blockIdx.x * 64;
    int gr0 = i0 + (w & 3) * 16 + rl, gr1 = gr0 + 8;
    float2 ac0 = g_AC[hd][gr0], ac1 = g_AC[hd][gr1];
    const unsigned* adjR0 = g_adjb + gr0 * 256;
    const unsigned* adjR1 = g_adjb + gr1 * 256;
    unsigned smbase = (unsigned)__cvta_generic_to_shared(sm);
    unsigned bdbase = (unsigned)__cvta_generic_to_shared(bdAll);

    float acc[NTT][4];
#pragma unroll
    for (int i = 0; i < NTT; i++)
#pragma unroll
        for (int j = 0; j < 4; j++) acc[i][j] = 0.f;
    float ls0 = 0.f, ls1 = 0.f;

    auto preload = [&](int jc, int s) {
        for (int t = tid; t < 64 * (LD / 8); t += 256) {
            int r = t / (LD / 8), c8 = (t % (LD / 8)) * 8;
            cpa16(smbase + (s * STAGE + r * PADL + c8) * 2,
                  &WH[(size_t)(jc + r) * LD + c8]);
            cpa16(smbase + (s * STAGE + 64 * PADL + r * PADL + c8) * 2,
                  &WL[(size_t)(jc + r) * LD + c8]);
        }
        if (tid < NH * 32) {
            int hh = tid >> 5, off = (tid & 31) * 2;
            cpa16(bdbase + (s * NH * 64 + hh * 64 + off) * 8,
                  &g_BD[hh][jc + off]);
        }
    };

    preload(0, 0);
    CPA_COMMIT();
    unsigned mA0 = adjR0[0], mA1 = adjR0[1];
    unsigned mB0 = adjR1[0], mB1 = adjR1[1];

    for (int c = 0; c < Nn / 64; c++) {
        int s = c & 1;
        if (c + 1 < Nn / 64) {
            preload((c + 1) * 64, s ^ 1);
            CPA_COMMIT();
            asm volatile("cp.async.wait_group 1;\n");
        } else {
            asm volatile("cp.async.wait_group 0;\n");
        }
        __syncthreads();
        unsigned cA0 = mA0, cA1 = mA1, cB0 = mB0, cB1 = mB1;
        if (c + 1 < Nn / 64) {
            int b = (c + 1) * 2;
            mA0 = adjR0[b]; mA1 = adjR0[b + 1];
            mB0 = adjR1[b]; mB1 = adjR1[b + 1];
        }
        __half* WHs = sm + s * STAGE;
        __half* WLs = WHs + 64 * PADL;
        float2* bdS = bdAll + s * NH * 64;
#pragma unroll
        for (int sub = 0; sub < 4; sub++) {
            unsigned mw0 = (sub < 2) ? cA0 : cA1;
            unsigned mw1 = (sub < 2) ? cB0 : cB1;
            int o = (sub & 1) * 16;
            float4 bd0 = *(float4*)&bdS[hd * 64 + sub * 16 + 2 * q];
            float4 bd8 = *(float4*)&bdS[hd * 64 + sub * 16 + 2 * q + 8];
            float p00 = (mw0 >> (o + 2 * q)) & 1 ? fmaxf(ac0.x * bd0.x, ac0.y * bd0.y) : 0.f;
            float p01 = (mw0 >> (o + 2 * q + 1)) & 1 ? fmaxf(ac0.x * bd0.z, ac0.y * bd0.w) : 0.f;
            float p02 = (mw0 >> (o + 2 * q + 8)) & 1 ? fmaxf(ac0.x * bd8.x, ac0.y * bd8.y) : 0.f;
            float p03 = (mw0 >> (o + 2 * q + 9)) & 1 ? fmaxf(ac0.x * bd8.z, ac0.y * bd8.w) : 0.f;
            float p10 = (mw1 >> (o + 2 * q)) & 1 ? fmaxf(ac1.x * bd0.x, ac1.y * bd0.y) : 0.f;
            float p11 = (mw1 >> (o + 2 * q + 1)) & 1 ? fmaxf(ac1.x * bd0.z, ac1.y * bd0.w) : 0.f;
            float p12 = (mw1 >> (o + 2 * q + 8)) & 1 ? fmaxf(ac1.x * bd8.x, ac1.y * bd8.y) : 0.f;
            float p13 = (mw1 >> (o + 2 * q + 9)) & 1 ? fmaxf(ac1.x * bd8.z, ac1.y * bd8.w) : 0.f;
            ls0 += p00 + p01 + p02 + p03;
            ls1 += p10 + p11 + p12 + p13;
            unsigned aH[4], aL[4];
            split2(p00, p01, aH[0], aL[0]);
            split2(p10, p11, aH[1], aL[1]);
            split2(p02, p03, aH[2], aL[2]);
            split2(p12, p13, aH[3], aL[3]);
            int krow = sub * 16 + (lane & 15), cofs = (lane >> 4) * 8;
#pragma unroll
            for (int ng = 0; ng < NTT / 2; ng++) {
                int n0 = nb + ng * 16;
                unsigned bh0, bh1, bh2, bh3, bl0, bl1, bl2, bl3;
                ldsm4t(bh0, bh1, bh2, bh3, &WHs[krow * PADL + n0 + cofs]);
                ldsm4t(bl0, bl1, bl2, bl3, &WLs[krow * PADL + n0 + cofs]);
                mma16816(acc[2 * ng], aH[0], aH[1], aH[2], aH[3], bh0, bh1);
                mma16816(acc[2 * ng], aL[0], aL[1], aL[2], aL[3], bh0, bh1);
                mma16816(acc[2 * ng], aH[0], aH[1], aH[2], aH[3], bl0, bl1);
                mma16816(acc[2 * ng + 1], aH[0], aH[1], aH[2], aH[3], bh2, bh3);
                mma16816(acc[2 * ng + 1], aL[0], aL[1], aL[2], aL[3], bh2, bh3);
                mma16816(acc[2 * ng + 1], aH[0], aH[1], aH[2], aH[3], bl2, bl3);
            }
        }
        __syncthreads();
    }
    ls0 += __shfl_xor_sync(0xffffffffu, ls0, 1);
    ls0 += __shfl_xor_sync(0xffffffffu, ls0, 2);
    ls1 += __shfl_xor_sync(0xffffffffu, ls1, 1);
    ls1 += __shfl_xor_sync(0xffffffffu, ls1, 2);
    float inv0 = 1.f / ls0, inv1 = 1.f / ls1;
    float* outA = (NH == 2) ? &g_h[0][0] : &g_mu[0][0];
#pragma unroll
    for (int nt = 0; nt < NTT; nt++) {
        int c = nb + nt * 8 + 2 * q;
        float m00 = eluf(acc[nt][0] * inv0), m01 = eluf(acc[nt][1] * inv0);
        float m10 = eluf(acc[nt][2] * inv1), m11 = eluf(acc[nt][3] * inv1);
        *(float2*)&outA[(size_t)gr0 * LD + c] = make_float2(m00, m01);
        *(float2*)&outA[(size_t)gr1 * LD + c] = make_float2(m10, m11);
        if (NH == 1) {
            *(float2*)&outB[(size_t)gr0 * LD + c] = make_float2(m00, m01);
            *(float2*)&outB[(size_t)gr1 * LD + c] = make_float2(m10, m11);
            unsigned h0, l0, h1, l1;
            split2(m00, m01, h0, l0);
            split2(m10, m11, h1, l1);
            *(unsigned*)&g_muh[(size_t)gr0 * 64 + c] = h0;
            *(unsigned*)&g_mul[(size_t)gr0 * 64 + c] = l0;
            *(unsigned*)&g_muh[(size_t)gr1 * 64 + c] = h1;
            *(unsigned*)&g_mul[(size_t)gr1 * 64 + c] = l1;
        }
    }
}

// ---------------- K5: Wh2 = h @ W_out ----------------
__global__ void __launch_bounds__(256) k_gemm2(const float* __restrict__ Wout) {
    __shared__ float hs[4][256];
    __shared__ float ws[64][64];
    int tid = threadIdx.x, i0 = blockIdx.x * 4;
    int r = tid >> 6, c4 = (tid & 63) * 4;
    *(float4*)&hs[r][c4] = *(const float4*)&g_h[i0 + r][c4];
    int c = tid & 63;
    float acc = 0.f;
    for (int k0 = 0; k0 < 256; k0 += 64) {
        __syncthreads();
#pragma unroll
        for (int p = 0; p < 4; p++) {
            int idx = tid + p * 256, kk = idx >> 4, cc = (idx & 15) * 4;
            *(float4*)&ws[kk][cc] = *(const float4*)&Wout[(size_t)(k0 + kk) * NCLS + cc];
        }
        __syncthreads();
#pragma unroll
        for (int kk = 0; kk < 64; kk++) acc += hs[r][k0 + kk] * ws[kk][c];
    }
    g_Wh2[i0 + r][c] = acc;
}

// ---------------- K6: layer-2 f1,f2 + max + split ----------------
__global__ void __launch_bounds__(256) k_fb(const float* __restrict__ a_out) {
    int tid = threadIdx.x, w = tid >> 5, lane = tid & 31;
    int row = blockIdx.x * 8 + w;
    float2 v = *(const float2*)&g_Wh2[row][lane * 2];
    unsigned hh, ll;
    split2(v.x, v.y, hh, ll);
    *(unsigned*)&g_W2h[(size_t)row * 64 + lane * 2] = hh;
    *(unsigned*)&g_W2l[(size_t)row * 64 + lane * 2] = ll;
    float2 as = *(const float2*)&a_out[lane * 2];
    float2 at = *(const float2*)&a_out[NCLS + lane * 2];
    float f1 = v.x * as.x + v.y * as.y;
    float f2 = v.x * at.x + v.y * at.y;
#pragma unroll
    for (int off = 16; off; off >>= 1) {
        f1 += __shfl_xor_sync(0xffffffffu, f1, off);
        f2 += __shfl_xor_sync(0xffffffffu, f2, off);
    }
    __shared__ float sm[8];
    if (lane == 0) { g_f1b[row] = f1; g_f2b[row] = f2; sm[w] = f2; }
    __syncthreads();
    if (tid == 0) {
        float m = sm[0];
#pragma unroll
        for (int k = 1; k < 8; k++) m = fmaxf(m, sm[k]);
        atomicMax(&g_max2, enc_f(m));
    }
}

// ---------------- recon = mu @ mu^T on tensor cores ----------------
__global__ void __launch_bounds__(256) k_recon_tc(float* __restrict__ out) {
    extern __shared__ __half sm[];
    __half* AH = sm;
    __half* AL = AH + 128 * 72;
    __half* BH = AL + 128 * 72;
    __half* BL = BH + 128 * 72;
    int tid = threadIdx.x, w = tid >> 5, lane = tid & 31;
    int i0 = blockIdx.y * 128, j0 = blockIdx.x * 128;
    for (int t = tid; t < 1024; t += 256) {
        int r = t >> 3, c8 = (t & 7) * 8;
        *(int4*)&AH[r * 72 + c8] = *(const int4*)&g_muh[(size_t)(i0 + r) * 64 + c8];
        *(int4*)&AL[r * 72 + c8] = *(const int4*)&g_mul[(size_t)(i0 + r) * 64 + c8];
        *(int4*)&BH[r * 72 + c8] = *(const int4*)&g_muh[(size_t)(j0 + r) * 64 + c8];
        *(int4*)&BL[r * 72 + c8] = *(const int4*)&g_mul[(size_t)(j0 + r) * 64 + c8];
    }
    __syncthreads();
    int wm = w & 3, wn = w >> 2;
    float acc[2][8][4] = {};
#pragma unroll
    for (int ks = 0; ks < 4; ks++) {
        int k0 = ks * 16;
        unsigned ah[2][4], al[2][4];
#pragma unroll
        for (int mt = 0; mt < 2; mt++) {
            int arow = wm * 32 + mt * 16 + (lane & 15);
            int ac = k0 + (lane >> 4) * 8;
            ldsm4(ah[mt][0], ah[mt][1], ah[mt][2], ah[mt][3], &AH[arow * 72 + ac]);
            ldsm4(al[mt][0], al[mt][1], al[mt][2], al[mt][3], &AL[arow * 72 + ac]);
        }
#pragma unroll
        for (int ng = 0; ng < 4; ng++) {
            int brow = wn * 64 + ng * 16 + (lane & 7) + ((lane >> 4) << 3);
            int bc = k0 + ((lane >> 3) & 1) * 8;
            unsigned bh0, bh1, bh2, bh3, bl0, bl1, bl2, bl3;
            ldsm4(bh0, bh1, bh2, bh3, &BH[brow * 72 + bc]);
            ldsm4(bl0, bl1, bl2, bl3, &BL[brow * 72 + bc]);
#pragma unroll
            for (int mt = 0; mt < 2; mt++) {
                mma16816(acc[mt][2 * ng], ah[mt][0], ah[mt][1], ah[mt][2], ah[mt][3], bh0, bh1);
                mma16816(acc[mt][2 * ng], al[mt][0], al[mt][1], al[mt][2], al[mt][3], bh0, bh1);
                mma16816(acc[mt][2 * ng], ah[mt][0], ah[mt][1], ah[mt][2], ah[mt][3], bl0, bl1);
                mma16816(acc[mt][2 * ng + 1], ah[mt][0], ah[mt][1], ah[mt][2], ah[mt][3], bh2, bh3);
                mma16816(acc[mt][2 * ng + 1], al[mt][0], al[mt][1], al[mt][2], al[mt][3], bh2, bh3);
                mma16816(acc[mt][2 * ng + 1], ah[mt][0], ah[mt][1], ah[mt][2], ah[mt][3], bl2, bl3);
            }
        }
    }
#pragma unroll
    for (int mt = 0; mt < 2; mt++) {
        int gi = i0 + wm * 32 + mt * 16 + (lane >> 2);
#pragma unroll
        for (int nt = 0; nt < 8; nt++) {
            int gj = j0 + wn * 64 + nt * 8 + 2 * (lane & 3);
            *(float2*)&out[(size_t)gi * Nn + gj] = make_float2(acc[mt][nt][0], acc[mt][nt][1]);
            *(float2*)&out[(size_t)(gi + 8) * Nn + gj] = make_float2(acc[mt][nt][2], acc[mt][nt][3]);
        }
    }
}

// ---------------- K9: class_pre ----------------
__global__ void __launch_bounds__(256) k_class(const float* __restrict__ W1,
                                               float* __restrict__ outc) {
    __shared__ float w1s[NCLS * CPRE];
    int tid = threadIdx.x, w = tid >> 5, lane = tid & 31;
    *(float4*)&w1s[tid * 4] = *(const float4*)&W1[tid * 4];
    __syncthreads();
    int row = blockIdx.x * 8 + w;
    int c = lane & 15, half = lane >> 4;
    float acc = 0.f;
#pragma unroll
    for (int k = 0; k < 32; k++) {
        int kk = half * 32 + k;
        acc += g_mu[row][kk] * w1s[kk * CPRE + c];
    }
    acc += __shfl_xor_sync(0xffffffffu, acc, 16);
    float m = acc;
#pragma unroll
    for (int off = 8; off; off >>= 1) m = fmaxf(m, __shfl_xor_sync(0xffffffffu, m, off));
    float e = __expf(acc - m);
    float s = e;
#pragma unroll
    for (int off = 8; off; off >>= 1) s += __shfl_xor_sync(0xffffffffu, s, off);
    if (lane < 16) outc[(size_t)row * CPRE + c] = e / s;
}

// ---------------- launch ----------------
extern "C" void kernel_launch(void* const* d_in, const int* in_sizes, int n_in,
                              void* d_out, int out_size) {
    const float* x       = (const float*)d_in[0];
    const int*   adj     = (const int*)d_in[1];
    const float* W_heads = (const float*)d_in[2];
    const float* a_heads = (const float*)d_in[3];
    const float* W_out   = (const float*)d_in[4];
    const float* a_out   = (const float*)d_in[5];
    const float* W1      = (const float*)d_in[6];
    float* out = (float*)d_out;
    float* out_mu    = out + (size_t)Nn * Nn;
    float* out_class = out_mu + (size_t)Nn * NCLS;

    const int SM1 = 2 * (2 * 64 * 264) * 2 + 2 * 2 * 64 * 8;   // 137216
    const int SM2 = 2 * (2 * 64 * 72) * 2 + 2 * 1 * 64 * 8;    //  37888
    const int SMR = 4 * 128 * 72 * 2;                          //  73728
    static bool attr_done = false;
    if (!attr_done) {
        cudaFuncSetAttribute(k_attn_tc<2, 128>, cudaFuncAttributeMaxDynamicSharedMemorySize, SM1);
        cudaFuncSetAttribute(k_attn_tc<1, 64>, cudaFuncAttributeMaxDynamicSharedMemorySize, SM2);
        cudaFuncSetAttribute(k_recon_tc, cudaFuncAttributeMaxDynamicSharedMemorySize, SMR);
        attr_done = true;
    }

    k_init<<<1, 1>>>();
    k_pack<<<Nn, 256>>>(adj);
    k_splitx<<<Nn * FIN / 1024, 256>>>(x);
    k_gemm1_tc<<<dim3(Nn / 128, 2), 256>>>(W_heads);
    k_fheads<<<Nn / 8, 256>>>(a_heads);
    k_acbd1<<<Nn / 256, 256>>>();
    k_attn_tc<2, 128><<<Nn / 64, 256, SM1>>>(nullptr);
    k_gemm2<<<Nn / 4, 256>>>(W_out);
    k_fb<<<Nn / 8, 256>>>(a_out);
    k_acbd2<<<Nn / 256, 256>>>();
    k_attn_tc<1, 64><<<Nn / 64, 256, SM2>>>(out_mu);
    k_recon_tc<<<dim3(Nn / 128, Nn / 128), 256, SMR>>>(out);
    k_class<<<Nn / 8, 256>>>(W1, out_class);
}